// round 2
// baseline (speedup 1.0000x reference)
#include <cuda_runtime.h>

// Problem constants (fixed by setup_inputs)
#define NS      51      // hidden size
#define NSP     52      // padded hidden (units and K padded to even)
#define KP      26      // k-pairs (52/2)
#define TSEQ    2048
#define BATCH   8192
#define MROWS   64      // batch rows per CTA
#define NTHREADS 256
#define HSTRIDE 54      // h-row stride in floats (conflict-free LDS.64 across lanes)
#define CHUNK   32      // x/y staging chunk (timesteps)
#define XSTRIDE 33      // padded chunk stride

// Weight SMEM layout: [kp][u][half] as ulonglong2 (= float4 of two f32x2 gate pairs).
// half=0 -> gates {i,f}, half=1 -> gates {g,o}.
struct Smem {
    ulonglong2 W1[KP * NSP * 2];  // W_hh1
    ulonglong2 W2[KP * NSP * 2];  // W_ih2
    ulonglong2 W3[KP * NSP * 2];  // W_hh2
    float4 B1v[NSP];              // layer1 bias per gate (b_ih1+b_hh1)
    float4 XWv[NSP];              // W_ih1 per gate (input dim = 1)
    float4 B2v[NSP];              // layer2 bias per gate
    float  WL[NSP];               // W_lin
    float  H1[MROWS * HSTRIDE];
    float  H2[MROWS * HSTRIDE];
    float  XS[MROWS * XSTRIDE];
    float  YS[MROWS * XSTRIDE];
};

__device__ __forceinline__ unsigned long long ffma2(unsigned long long a,
                                                    unsigned long long b,
                                                    unsigned long long c) {
    unsigned long long d;
    asm("fma.rn.f32x2 %0, %1, %2, %3;" : "=l"(d) : "l"(a), "l"(b), "l"(c));
    return d;
}
__device__ __forceinline__ unsigned long long pack2(float lo, float hi) {
    unsigned long long r;
    asm("mov.b64 %0, {%1, %2};" : "=l"(r) : "f"(lo), "f"(hi));
    return r;
}
__device__ __forceinline__ float hsum2(unsigned long long a) {
    float lo, hi;
    asm("mov.b64 {%0, %1}, %2;" : "=f"(lo), "=f"(hi) : "l"(a));
    return lo + hi;
}
__device__ __forceinline__ float fsigmoid(float x) {
    float e;
    asm("ex2.approx.ftz.f32 %0, %1;" : "=f"(e) : "f"(-1.4426950408889634f * x));
    float r;
    asm("rcp.approx.ftz.f32 %0, %1;" : "=f"(r) : "f"(1.0f + e));
    return r;
}
__device__ __forceinline__ float ftanh(float x) {
    return fmaf(2.0f, fsigmoid(2.0f * x), -1.0f);
}

// Pack a [4*NS, NS] weight matrix into SMEM layout [kp][u][half].
// dst[(kp*NSP + u)*2 + half] = float4{ Wg0[u][2kp], Wg0[u][2kp+1], Wg1[u][2kp], Wg1[u][2kp+1] }
// where (g0,g1) = (i,f) for half=0 and (g,o) for half=1. Pads (u>=NS, k>=NS) are zero.
__device__ void fill_w(ulonglong2* dst, const float* __restrict__ W, int tid) {
    for (int idx = tid; idx < KP * NSP * 2; idx += NTHREADS) {
        int kp   = idx / (NSP * 2);
        int rem  = idx - kp * (NSP * 2);
        int u    = rem >> 1;
        int half = rem & 1;
        int g0 = half * 2, g1 = g0 + 1;
        int k0 = kp * 2,   k1 = k0 + 1;
        float4 v = make_float4(0.f, 0.f, 0.f, 0.f);
        if (u < NS) {
            const float* r0 = W + (g0 * NS + u) * NS;
            const float* r1 = W + (g1 * NS + u) * NS;
            v.x = r0[k0];
            v.y = (k1 < NS) ? r0[k1] : 0.f;
            v.z = r1[k0];
            v.w = (k1 < NS) ? r1[k1] : 0.f;
        }
        reinterpret_cast<float4*>(dst)[idx] = v;
    }
}

__global__ __launch_bounds__(NTHREADS, 1)
void lstm2_seq_kernel(const float* __restrict__ x,
                      const float* __restrict__ Wih1, const float* __restrict__ Whh1,
                      const float* __restrict__ bih1, const float* __restrict__ bhh1,
                      const float* __restrict__ Wih2, const float* __restrict__ Whh2,
                      const float* __restrict__ bih2, const float* __restrict__ bhh2,
                      const float* __restrict__ Wlin, const float* __restrict__ blin,
                      float* __restrict__ out) {
    extern __shared__ char smraw[];
    Smem* s = reinterpret_cast<Smem*>(smraw);
    const int tid = threadIdx.x;

    // ---- one-time SMEM setup ----
    fill_w(s->W1, Whh1, tid);
    fill_w(s->W2, Wih2, tid);
    fill_w(s->W3, Whh2, tid);
    for (int u = tid; u < NSP; u += NTHREADS) {
        float4 b1 = make_float4(0.f, 0.f, 0.f, 0.f);
        float4 xw = b1, b2 = b1;
        float wl = 0.f;
        if (u < NS) {
            b1 = make_float4(bih1[u] + bhh1[u],
                             bih1[NS + u] + bhh1[NS + u],
                             bih1[2 * NS + u] + bhh1[2 * NS + u],
                             bih1[3 * NS + u] + bhh1[3 * NS + u]);
            xw = make_float4(Wih1[u], Wih1[NS + u], Wih1[2 * NS + u], Wih1[3 * NS + u]);
            b2 = make_float4(bih2[u] + bhh2[u],
                             bih2[NS + u] + bhh2[NS + u],
                             bih2[2 * NS + u] + bhh2[2 * NS + u],
                             bih2[3 * NS + u] + bhh2[3 * NS + u]);
            wl = Wlin[u];
        }
        s->B1v[u] = b1;
        s->XWv[u] = xw;
        s->B2v[u] = b2;
        s->WL[u]  = wl;
    }
    for (int i = tid; i < MROWS * HSTRIDE; i += NTHREADS) {
        s->H1[i] = 0.f;
        s->H2[i] = 0.f;
    }
    __syncthreads();

    // thread mapping: warp = 32 consecutive rows of one unit-group
    const int r  = tid & (MROWS - 1);   // row 0..63
    const int ug = tid >> 6;            // unit-group 0..3 (13 units each)
    const int u0 = ug * 13;
    const int rb = blockIdx.x * MROWS;
    const float bl = blin[0];

    float c1[13], c2[13];
#pragma unroll
    for (int i = 0; i < 13; i++) { c1[i] = 0.f; c2[i] = 0.f; }

    float* h1row = s->H1 + r * HSTRIDE;
    float* h2row = s->H2 + r * HSTRIDE;

    unsigned long long acc[13][4];   // per-unit {i,f,g,o} f32x2 accumulators

    for (int t = 0; t < TSEQ; t++) {
        if ((t & (CHUNK - 1)) == 0) {
            __syncthreads();
            if (t) {
                const int t0 = t - CHUNK;
                for (int idx = tid; idx < MROWS * CHUNK; idx += NTHREADS) {
                    int row = idx >> 5, c = idx & 31;
                    out[(long long)(rb + row) * TSEQ + t0 + c] = s->YS[row * XSTRIDE + c];
                }
            }
            for (int idx = tid; idx < MROWS * CHUNK; idx += NTHREADS) {
                int row = idx >> 5, c = idx & 31;
                s->XS[row * XSTRIDE + c] = x[(long long)(rb + row) * TSEQ + t + c];
            }
            __syncthreads();
        }
        const float xt = s->XS[r * XSTRIDE + (t & (CHUNK - 1))];

        // ---- layer 1: gates1 = h1 @ W_hh1^T + x_t*W_ih1 + b1 ----
#pragma unroll
        for (int uu = 0; uu < 13; uu++) {
            const float4 bb = s->B1v[u0 + uu];
            const float4 xw = s->XWv[u0 + uu];
            acc[uu][0] = pack2(bb.x, xt * xw.x);
            acc[uu][1] = pack2(bb.y, xt * xw.y);
            acc[uu][2] = pack2(bb.z, xt * xw.z);
            acc[uu][3] = pack2(bb.w, xt * xw.w);
        }
        for (int kp = 0; kp < KP; kp++) {
            const unsigned long long hp =
                *reinterpret_cast<const unsigned long long*>(h1row + 2 * kp);
            const ulonglong2* wk = s->W1 + (kp * NSP + u0) * 2;
#pragma unroll
            for (int uu = 0; uu < 13; uu++) {
                const ulonglong2 wA = wk[uu * 2 + 0];
                const ulonglong2 wB = wk[uu * 2 + 1];
                acc[uu][0] = ffma2(wA.x, hp, acc[uu][0]);
                acc[uu][1] = ffma2(wA.y, hp, acc[uu][1]);
                acc[uu][2] = ffma2(wB.x, hp, acc[uu][2]);
                acc[uu][3] = ffma2(wB.y, hp, acc[uu][3]);
            }
        }
        float h1n[13];
#pragma unroll
        for (int uu = 0; uu < 13; uu++) {
            const float gi = fsigmoid(hsum2(acc[uu][0]));
            const float gf = fsigmoid(hsum2(acc[uu][1]));
            const float gg = ftanh(hsum2(acc[uu][2]));
            const float go = fsigmoid(hsum2(acc[uu][3]));
            const float c = fmaf(gf, c1[uu], gi * gg);
            c1[uu] = c;
            h1n[uu] = go * ftanh(c);
        }
        __syncthreads();
#pragma unroll
        for (int uu = 0; uu < 13; uu++) h1row[u0 + uu] = h1n[uu];
        __syncthreads();

        // ---- layer 2: gates2 = h1_new @ W_ih2^T + h2 @ W_hh2^T + b2 ----
#pragma unroll
        for (int uu = 0; uu < 13; uu++) {
            const float4 bb = s->B2v[u0 + uu];
            acc[uu][0] = pack2(bb.x, 0.f);
            acc[uu][1] = pack2(bb.y, 0.f);
            acc[uu][2] = pack2(bb.z, 0.f);
            acc[uu][3] = pack2(bb.w, 0.f);
        }
        for (int kp = 0; kp < KP; kp++) {
            const unsigned long long hp1 =
                *reinterpret_cast<const unsigned long long*>(h1row + 2 * kp);
            const unsigned long long hp2 =
                *reinterpret_cast<const unsigned long long*>(h2row + 2 * kp);
            const ulonglong2* wk2 = s->W2 + (kp * NSP + u0) * 2;
            const ulonglong2* wk3 = s->W3 + (kp * NSP + u0) * 2;
#pragma unroll
            for (int uu = 0; uu < 13; uu++) {
                ulonglong2 wA = wk2[uu * 2 + 0];
                ulonglong2 wB = wk2[uu * 2 + 1];
                acc[uu][0] = ffma2(wA.x, hp1, acc[uu][0]);
                acc[uu][1] = ffma2(wA.y, hp1, acc[uu][1]);
                acc[uu][2] = ffma2(wB.x, hp1, acc[uu][2]);
                acc[uu][3] = ffma2(wB.y, hp1, acc[uu][3]);
                wA = wk3[uu * 2 + 0];
                wB = wk3[uu * 2 + 1];
                acc[uu][0] = ffma2(wA.x, hp2, acc[uu][0]);
                acc[uu][1] = ffma2(wA.y, hp2, acc[uu][1]);
                acc[uu][2] = ffma2(wB.x, hp2, acc[uu][2]);
                acc[uu][3] = ffma2(wB.y, hp2, acc[uu][3]);
            }
        }
        float h2n[13];
#pragma unroll
        for (int uu = 0; uu < 13; uu++) {
            const float gi = fsigmoid(hsum2(acc[uu][0]));
            const float gf = fsigmoid(hsum2(acc[uu][1]));
            const float gg = ftanh(hsum2(acc[uu][2]));
            const float go = fsigmoid(hsum2(acc[uu][3]));
            const float c = fmaf(gf, c2[uu], gi * gg);
            c2[uu] = c;
            h2n[uu] = go * ftanh(c);
        }
        __syncthreads();
#pragma unroll
        for (int uu = 0; uu < 13; uu++) h2row[u0 + uu] = h2n[uu];
        __syncthreads();

        // ---- projection: y = h2 . W_lin + b_lin (unit-group 0 threads) ----
        if (ug == 0) {
            float y = bl;
#pragma unroll
            for (int u = 0; u < NSP; u++) y = fmaf(h2row[u], s->WL[u], y);
            s->YS[r * XSTRIDE + (t & (CHUNK - 1))] = y;
        }
    }

    // final chunk flush
    __syncthreads();
    for (int idx = tid; idx < MROWS * CHUNK; idx += NTHREADS) {
        int row = idx >> 5, c = idx & 31;
        out[(long long)(rb + row) * TSEQ + (TSEQ - CHUNK) + c] = s->YS[row * XSTRIDE + c];
    }
}

extern "C" void kernel_launch(void* const* d_in, const int* in_sizes, int n_in,
                              void* d_out, int out_size) {
    const float* x    = (const float*)d_in[0];
    const float* Wih1 = (const float*)d_in[1];
    const float* Whh1 = (const float*)d_in[2];
    const float* bih1 = (const float*)d_in[3];
    const float* bhh1 = (const float*)d_in[4];
    const float* Wih2 = (const float*)d_in[5];
    const float* Whh2 = (const float*)d_in[6];
    const float* bih2 = (const float*)d_in[7];
    const float* bhh2 = (const float*)d_in[8];
    const float* Wlin = (const float*)d_in[9];
    const float* blin = (const float*)d_in[10];
    // d_in[11] = future (always 0) — unused

    cudaFuncSetAttribute(lstm2_seq_kernel,
                         cudaFuncAttributeMaxDynamicSharedMemorySize,
                         (int)sizeof(Smem));

    lstm2_seq_kernel<<<BATCH / MROWS, NTHREADS, sizeof(Smem)>>>(
        x, Wih1, Whh1, bih1, bhh1, Wih2, Whh2, bih2, bhh2, Wlin, blin,
        (float*)d_out);
}

// round 3
// speedup vs baseline: 1.0014x; 1.0014x over previous
#include <cuda_runtime.h>

// Problem constants (fixed by setup_inputs)
#define NS      51      // hidden size
#define NSP     52      // padded hidden (units and K padded to even)
#define KP      26      // k-pairs (52/2)
#define TSEQ    2048
#define BATCH   8192
#define MROWS   64      // batch rows per CTA
#define NTHREADS 256
#define HSTRIDE 54      // h-row stride in floats (conflict-free LDS.64 across lanes)
#define CHUNK   32      // x/y staging chunk (timesteps)
#define XSTRIDE 33      // padded chunk stride

// Weight SMEM layout: [kp][u][half] as ulonglong2 (= float4 of two f32x2 gate pairs).
// half=0 -> gates {i,f}, half=1 -> gates {g,o}.
struct Smem {
    ulonglong2 W1[KP * NSP * 2];  // W_hh1
    ulonglong2 W2[KP * NSP * 2];  // W_ih2
    ulonglong2 W3[KP * NSP * 2];  // W_hh2
    float4 B1v[NSP];              // layer1 bias per gate (b_ih1+b_hh1)
    float4 XWv[NSP];              // W_ih1 per gate (input dim = 1)
    float4 B2v[NSP];              // layer2 bias per gate
    float  WL[NSP];               // W_lin
    float  H1[MROWS * HSTRIDE];
    float  H2[MROWS * HSTRIDE];
    float  XS[MROWS * XSTRIDE];
    float  YS[MROWS * XSTRIDE];
};

__device__ __forceinline__ unsigned long long ffma2(unsigned long long a,
                                                    unsigned long long b,
                                                    unsigned long long c) {
    unsigned long long d;
    asm("fma.rn.f32x2 %0, %1, %2, %3;" : "=l"(d) : "l"(a), "l"(b), "l"(c));
    return d;
}
__device__ __forceinline__ unsigned long long pack2(float lo, float hi) {
    unsigned long long r;
    asm("mov.b64 %0, {%1, %2};" : "=l"(r) : "f"(lo), "f"(hi));
    return r;
}
__device__ __forceinline__ float hsum2(unsigned long long a) {
    float lo, hi;
    asm("mov.b64 {%0, %1}, %2;" : "=f"(lo), "=f"(hi) : "l"(a));
    return lo + hi;
}
__device__ __forceinline__ float fsigmoid(float x) {
    float e;
    asm("ex2.approx.ftz.f32 %0, %1;" : "=f"(e) : "f"(-1.4426950408889634f * x));
    float r;
    asm("rcp.approx.ftz.f32 %0, %1;" : "=f"(r) : "f"(1.0f + e));
    return r;
}
__device__ __forceinline__ float ftanh(float x) {
    return fmaf(2.0f, fsigmoid(2.0f * x), -1.0f);
}

// Pack a [4*NS, NS] weight matrix into SMEM layout [kp][u][half].
// dst[(kp*NSP + u)*2 + half] = float4{ Wg0[u][2kp], Wg0[u][2kp+1], Wg1[u][2kp], Wg1[u][2kp+1] }
// where (g0,g1) = (i,f) for half=0 and (g,o) for half=1. Pads (u>=NS, k>=NS) are zero.
__device__ void fill_w(ulonglong2* dst, const float* __restrict__ W, int tid) {
    for (int idx = tid; idx < KP * NSP * 2; idx += NTHREADS) {
        int kp   = idx / (NSP * 2);
        int rem  = idx - kp * (NSP * 2);
        int u    = rem >> 1;
        int half = rem & 1;
        int g0 = half * 2, g1 = g0 + 1;
        int k0 = kp * 2,   k1 = k0 + 1;
        float4 v = make_float4(0.f, 0.f, 0.f, 0.f);
        if (u < NS) {
            const float* r0 = W + (g0 * NS + u) * NS;
            const float* r1 = W + (g1 * NS + u) * NS;
            v.x = r0[k0];
            v.y = (k1 < NS) ? r0[k1] : 0.f;
            v.z = r1[k0];
            v.w = (k1 < NS) ? r1[k1] : 0.f;
        }
        reinterpret_cast<float4*>(dst)[idx] = v;
    }
}

__global__ __launch_bounds__(NTHREADS, 1)
void lstm2_seq_kernel(const float* __restrict__ x,
                      const float* __restrict__ Wih1, const float* __restrict__ Whh1,
                      const float* __restrict__ bih1, const float* __restrict__ bhh1,
                      const float* __restrict__ Wih2, const float* __restrict__ Whh2,
                      const float* __restrict__ bih2, const float* __restrict__ bhh2,
                      const float* __restrict__ Wlin, const float* __restrict__ blin,
                      float* __restrict__ out) {
    extern __shared__ char smraw[];
    Smem* s = reinterpret_cast<Smem*>(smraw);
    const int tid = threadIdx.x;

    // ---- one-time SMEM setup ----
    fill_w(s->W1, Whh1, tid);
    fill_w(s->W2, Wih2, tid);
    fill_w(s->W3, Whh2, tid);
    for (int u = tid; u < NSP; u += NTHREADS) {
        float4 b1 = make_float4(0.f, 0.f, 0.f, 0.f);
        float4 xw = b1, b2 = b1;
        float wl = 0.f;
        if (u < NS) {
            b1 = make_float4(bih1[u] + bhh1[u],
                             bih1[NS + u] + bhh1[NS + u],
                             bih1[2 * NS + u] + bhh1[2 * NS + u],
                             bih1[3 * NS + u] + bhh1[3 * NS + u]);
            xw = make_float4(Wih1[u], Wih1[NS + u], Wih1[2 * NS + u], Wih1[3 * NS + u]);
            b2 = make_float4(bih2[u] + bhh2[u],
                             bih2[NS + u] + bhh2[NS + u],
                             bih2[2 * NS + u] + bhh2[2 * NS + u],
                             bih2[3 * NS + u] + bhh2[3 * NS + u]);
            wl = Wlin[u];
        }
        s->B1v[u] = b1;
        s->XWv[u] = xw;
        s->B2v[u] = b2;
        s->WL[u]  = wl;
    }
    for (int i = tid; i < MROWS * HSTRIDE; i += NTHREADS) {
        s->H1[i] = 0.f;
        s->H2[i] = 0.f;
    }
    __syncthreads();

    // thread mapping: warp = 32 consecutive rows of one unit-group
    const int r  = tid & (MROWS - 1);   // row 0..63
    const int ug = tid >> 6;            // unit-group 0..3 (13 units each)
    const int u0 = ug * 13;
    const int rb = blockIdx.x * MROWS;
    const float bl = blin[0];

    float c1[13], c2[13];
#pragma unroll
    for (int i = 0; i < 13; i++) { c1[i] = 0.f; c2[i] = 0.f; }

    float* h1row = s->H1 + r * HSTRIDE;
    float* h2row = s->H2 + r * HSTRIDE;

    unsigned long long acc[13][4];   // per-unit {i,f,g,o} f32x2 accumulators

    for (int t = 0; t < TSEQ; t++) {
        if ((t & (CHUNK - 1)) == 0) {
            __syncthreads();
            if (t) {
                const int t0 = t - CHUNK;
                for (int idx = tid; idx < MROWS * CHUNK; idx += NTHREADS) {
                    int row = idx >> 5, c = idx & 31;
                    out[(long long)(rb + row) * TSEQ + t0 + c] = s->YS[row * XSTRIDE + c];
                }
            }
            for (int idx = tid; idx < MROWS * CHUNK; idx += NTHREADS) {
                int row = idx >> 5, c = idx & 31;
                s->XS[row * XSTRIDE + c] = x[(long long)(rb + row) * TSEQ + t + c];
            }
            __syncthreads();
        }
        const float xt = s->XS[r * XSTRIDE + (t & (CHUNK - 1))];

        // ---- layer 1: gates1 = h1 @ W_hh1^T + x_t*W_ih1 + b1 ----
#pragma unroll
        for (int uu = 0; uu < 13; uu++) {
            const float4 bb = s->B1v[u0 + uu];
            const float4 xw = s->XWv[u0 + uu];
            acc[uu][0] = pack2(bb.x, xt * xw.x);
            acc[uu][1] = pack2(bb.y, xt * xw.y);
            acc[uu][2] = pack2(bb.z, xt * xw.z);
            acc[uu][3] = pack2(bb.w, xt * xw.w);
        }
        for (int kp = 0; kp < KP; kp++) {
            const unsigned long long hp =
                *reinterpret_cast<const unsigned long long*>(h1row + 2 * kp);
            const ulonglong2* wk = s->W1 + (kp * NSP + u0) * 2;
#pragma unroll
            for (int uu = 0; uu < 13; uu++) {
                const ulonglong2 wA = wk[uu * 2 + 0];
                const ulonglong2 wB = wk[uu * 2 + 1];
                acc[uu][0] = ffma2(wA.x, hp, acc[uu][0]);
                acc[uu][1] = ffma2(wA.y, hp, acc[uu][1]);
                acc[uu][2] = ffma2(wB.x, hp, acc[uu][2]);
                acc[uu][3] = ffma2(wB.y, hp, acc[uu][3]);
            }
        }
        float h1n[13];
#pragma unroll
        for (int uu = 0; uu < 13; uu++) {
            const float gi = fsigmoid(hsum2(acc[uu][0]));
            const float gf = fsigmoid(hsum2(acc[uu][1]));
            const float gg = ftanh(hsum2(acc[uu][2]));
            const float go = fsigmoid(hsum2(acc[uu][3]));
            const float c = fmaf(gf, c1[uu], gi * gg);
            c1[uu] = c;
            h1n[uu] = go * ftanh(c);
        }
        __syncthreads();
#pragma unroll
        for (int uu = 0; uu < 13; uu++) h1row[u0 + uu] = h1n[uu];
        __syncthreads();

        // ---- layer 2: gates2 = h1_new @ W_ih2^T + h2 @ W_hh2^T + b2 ----
#pragma unroll
        for (int uu = 0; uu < 13; uu++) {
            const float4 bb = s->B2v[u0 + uu];
            acc[uu][0] = pack2(bb.x, 0.f);
            acc[uu][1] = pack2(bb.y, 0.f);
            acc[uu][2] = pack2(bb.z, 0.f);
            acc[uu][3] = pack2(bb.w, 0.f);
        }
        for (int kp = 0; kp < KP; kp++) {
            const unsigned long long hp1 =
                *reinterpret_cast<const unsigned long long*>(h1row + 2 * kp);
            const unsigned long long hp2 =
                *reinterpret_cast<const unsigned long long*>(h2row + 2 * kp);
            const ulonglong2* wk2 = s->W2 + (kp * NSP + u0) * 2;
            const ulonglong2* wk3 = s->W3 + (kp * NSP + u0) * 2;
#pragma unroll
            for (int uu = 0; uu < 13; uu++) {
                ulonglong2 wA = wk2[uu * 2 + 0];
                ulonglong2 wB = wk2[uu * 2 + 1];
                acc[uu][0] = ffma2(wA.x, hp1, acc[uu][0]);
                acc[uu][1] = ffma2(wA.y, hp1, acc[uu][1]);
                acc[uu][2] = ffma2(wB.x, hp1, acc[uu][2]);
                acc[uu][3] = ffma2(wB.y, hp1, acc[uu][3]);
                wA = wk3[uu * 2 + 0];
                wB = wk3[uu * 2 + 1];
                acc[uu][0] = ffma2(wA.x, hp2, acc[uu][0]);
                acc[uu][1] = ffma2(wA.y, hp2, acc[uu][1]);
                acc[uu][2] = ffma2(wB.x, hp2, acc[uu][2]);
                acc[uu][3] = ffma2(wB.y, hp2, acc[uu][3]);
            }
        }
        float h2n[13];
#pragma unroll
        for (int uu = 0; uu < 13; uu++) {
            const float gi = fsigmoid(hsum2(acc[uu][0]));
            const float gf = fsigmoid(hsum2(acc[uu][1]));
            const float gg = ftanh(hsum2(acc[uu][2]));
            const float go = fsigmoid(hsum2(acc[uu][3]));
            const float c = fmaf(gf, c2[uu], gi * gg);
            c2[uu] = c;
            h2n[uu] = go * ftanh(c);
        }
        __syncthreads();
#pragma unroll
        for (int uu = 0; uu < 13; uu++) h2row[u0 + uu] = h2n[uu];
        __syncthreads();

        // ---- projection: y = h2 . W_lin + b_lin (unit-group 0 threads) ----
        if (ug == 0) {
            float y = bl;
#pragma unroll
            for (int u = 0; u < NSP; u++) y = fmaf(h2row[u], s->WL[u], y);
            s->YS[r * XSTRIDE + (t & (CHUNK - 1))] = y;
        }
    }

    // final chunk flush
    __syncthreads();
    for (int idx = tid; idx < MROWS * CHUNK; idx += NTHREADS) {
        int row = idx >> 5, c = idx & 31;
        out[(long long)(rb + row) * TSEQ + (TSEQ - CHUNK) + c] = s->YS[row * XSTRIDE + c];
    }
}

extern "C" void kernel_launch(void* const* d_in, const int* in_sizes, int n_in,
                              void* d_out, int out_size) {
    const float* x    = (const float*)d_in[0];
    const float* Wih1 = (const float*)d_in[1];
    const float* Whh1 = (const float*)d_in[2];
    const float* bih1 = (const float*)d_in[3];
    const float* bhh1 = (const float*)d_in[4];
    const float* Wih2 = (const float*)d_in[5];
    const float* Whh2 = (const float*)d_in[6];
    const float* bih2 = (const float*)d_in[7];
    const float* bhh2 = (const float*)d_in[8];
    const float* Wlin = (const float*)d_in[9];
    const float* blin = (const float*)d_in[10];
    // d_in[11] = future (always 0) — unused

    cudaFuncSetAttribute(lstm2_seq_kernel,
                         cudaFuncAttributeMaxDynamicSharedMemorySize,
                         (int)sizeof(Smem));

    lstm2_seq_kernel<<<BATCH / MROWS, NTHREADS, sizeof(Smem)>>>(
        x, Wih1, Whh1, bih1, bhh1, Wih2, Whh2, bih2, bhh2, Wlin, blin,
        (float*)d_out);
}

// round 5
// speedup vs baseline: 5.8220x; 5.8141x over previous
#include <cuda_runtime.h>
#include <cuda_fp16.h>
#include <cstdint>

#define NS    51
#define ROWS  64
#define TSEQ  2048
#define BATCH 8192
#define NCTA  (BATCH / ROWS)
#define NTH   256
#define NTILE 26
#define KC1   4
#define KC2   7
#define ST1   72
#define ST2   120
#define CHUNK 16
#define XSTR  17

#define OFF_A1   0
#define OFF_A2   9216
#define OFF_B1F  24576
#define OFF_B2F  51200
#define OFF_XS   97792
#define OFF_YS   102144
#define OFF_YP   106496
#define OFF_WL   107520
#define SMEM_BYTES 107904

__device__ __forceinline__ uint32_t smem_u32(const void* p) {
    uint32_t a;
    asm("{ .reg .u64 t; cvta.to.shared.u64 t, %1; cvt.u32.u64 %0, t; }" : "=r"(a) : "l"(p));
    return a;
}
__device__ __forceinline__ void sts16h(uint32_t a, float v) {
    unsigned short h = __half_as_ushort(__float2half_rn(v));
    asm volatile("st.shared.b16 [%0], %1;" :: "r"(a), "h"(h) : "memory");
}
__device__ __forceinline__ void sts32(uint32_t a, float v) {
    asm volatile("st.shared.b32 [%0], %1;" :: "r"(a), "f"(v) : "memory");
}
__device__ __forceinline__ void sts32u(uint32_t a, uint32_t v) {
    asm volatile("st.shared.b32 [%0], %1;" :: "r"(a), "r"(v) : "memory");
}
__device__ __forceinline__ float lds32(uint32_t a) {
    float v;
    asm volatile("ld.shared.b32 %0, [%1];" : "=f"(v) : "r"(a));
    return v;
}
__device__ __forceinline__ uint32_t lds32u(uint32_t a) {
    uint32_t v;
    asm volatile("ld.shared.b32 %0, [%1];" : "=r"(v) : "r"(a));
    return v;
}
__device__ __forceinline__ void lds64u(uint32_t& v0, uint32_t& v1, uint32_t a) {
    asm volatile("ld.shared.v2.b32 {%0,%1}, [%2];" : "=r"(v0), "=r"(v1) : "r"(a));
}
__device__ __forceinline__ void hmma(float* d, const uint32_t* a, uint32_t b0, uint32_t b1) {
    asm volatile(
        "mma.sync.aligned.m16n8k16.row.col.f32.f16.f16.f32 "
        "{%0,%1,%2,%3}, {%4,%5,%6,%7}, {%8,%9}, {%0,%1,%2,%3};"
        : "+f"(d[0]), "+f"(d[1]), "+f"(d[2]), "+f"(d[3])
        : "r"(a[0]), "r"(a[1]), "r"(a[2]), "r"(a[3]), "r"(b0), "r"(b1));
}
__device__ __forceinline__ float fsig(float x) {
    float e, r;
    asm("ex2.approx.ftz.f32 %0, %1;" : "=f"(e) : "f"(-1.4426950408889634f * x));
    asm("rcp.approx.ftz.f32 %0, %1;" : "=f"(r) : "f"(1.0f + e));
    return r;
}
__device__ __forceinline__ float ftanh_(float x) {
    return fmaf(2.f, fsig(2.f * x), -1.f);
}

__device__ float w1val(int n, int k, const float* Whh1, const float* Wih1,
                       const float* bih1, const float* bhh1) {
    int u = n >> 2, g = n & 3;
    if (u >= NS) return 0.f;
    int gu = g * NS + u;
    if (k < NS) return Whh1[gu * NS + k];
    if (k == 52) return Wih1[gu];
    if (k == 53) return bih1[gu] + bhh1[gu];
    return 0.f;
}
__device__ float w2val(int n, int k, const float* Wih2, const float* Whh2,
                       const float* bih2, const float* bhh2) {
    int u = n >> 2, g = n & 3;
    if (u >= NS) return 0.f;
    int gu = g * NS + u;
    if (k < NS) return Wih2[gu * NS + k];
    if (k >= 52 && k - 52 < NS) return Whh2[gu * NS + (k - 52)];
    if (k == 104) return bih2[gu] + bhh2[gu];
    return 0.f;
}

extern __shared__ char smraw[];

__global__ __launch_bounds__(NTH, 1)
void lstm2_hmma_kernel(const float* __restrict__ x,
                       const float* __restrict__ Wih1, const float* __restrict__ Whh1,
                       const float* __restrict__ bih1, const float* __restrict__ bhh1,
                       const float* __restrict__ Wih2, const float* __restrict__ Whh2,
                       const float* __restrict__ bih2, const float* __restrict__ bhh2,
                       const float* __restrict__ Wlin, const float* __restrict__ blin,
                       float* __restrict__ out) {
    const uint32_t s0 = smem_u32(smraw);
    const int tid = threadIdx.x;
    const int wid = tid >> 5;
    const int lane = tid & 31;

    for (int i = tid; i < OFF_B1F / 4; i += NTH) sts32(s0 + i * 4, 0.f);
    for (int idx = tid; idx < NTILE * KC1 * 64; idx += NTH) {
        int w = idx & 1, ln = (idx >> 1) & 31, kc = (idx >> 6) & 3, nt = idx >> 8;
        int n = nt * 8 + (ln >> 2);
        int k = kc * 16 + (ln & 3) * 2 + w * 8;
        __half2 hv = __floats2half2_rn(w1val(n, k, Whh1, Wih1, bih1, bhh1),
                                       w1val(n, k + 1, Whh1, Wih1, bih1, bhh1));
        sts32u(s0 + OFF_B1F + idx * 4, *reinterpret_cast<uint32_t*>(&hv));
    }
    for (int idx = tid; idx < NTILE * KC2 * 64; idx += NTH) {
        int w = idx & 1, ln = (idx >> 1) & 31;
        int r = idx >> 6;
        int kc = r % KC2, nt = r / KC2;
        int n = nt * 8 + (ln >> 2);
        int k = kc * 16 + (ln & 3) * 2 + w * 8;
        __half2 hv = __floats2half2_rn(w2val(n, k, Wih2, Whh2, bih2, bhh2),
                                       w2val(n, k + 1, Wih2, Whh2, bih2, bhh2));
        sts32u(s0 + OFF_B2F + ((nt * KC2 + kc) * 64 + ln * 2 + w) * 4,
               *reinterpret_cast<uint32_t*>(&hv));
    }
    if (tid < ROWS) {
        sts16h(s0 + OFF_A1 + (tid * ST1 + 53) * 2, 1.f);
        sts16h(s0 + OFF_A2 + (tid * ST2 + 104) * 2, 1.f);
    }
    for (int u = tid; u < 52; u += NTH)
        sts32(s0 + OFF_WL + u * 4, (u < NS) ? Wlin[u] : 0.f);
    __syncthreads();

    const int mt = wid & 3;
    const int nh = wid >> 2;
    const int ptid = nh * 32 + lane;
    const int barid = mt + 1;
    const bool odd = lane & 1;
    const int rowE = mt * 16 + (lane >> 2) + (odd ? 8 : 0);
    const int ubase = 26 * nh + ((lane >> 1) & 1);
    const long long rb = (long long)blockIdx.x * ROWS;
    const float bl = blin[0];

    const uint32_t a1p = s0 + OFF_A1 + (mt * 16 + (lane >> 2)) * ST1 * 2 + (lane & 3) * 4;
    const uint32_t a2p = s0 + OFF_A2 + (mt * 16 + (lane >> 2)) * ST2 * 2 + (lane & 3) * 4;
    const uint32_t b1p = s0 + OFF_B1F + (nh * 13 * KC1 * 64 + lane * 2) * 4;
    const uint32_t b2p = s0 + OFF_B2F + (nh * 13 * KC2 * 64 + lane * 2) * 4;
    const uint32_t hw1 = s0 + OFF_A1 + rowE * ST1 * 2 + ubase * 2;
    const uint32_t hw2 = s0 + OFF_A2 + rowE * ST2 * 2 + ubase * 2;

    float wl[13];
#pragma unroll
    for (int j = 0; j < 13; j++) wl[j] = lds32(s0 + OFF_WL + (ubase + 2 * j) * 4);

    float c1[13], c2[13];
#pragma unroll
    for (int i = 0; i < 13; i++) { c1[i] = 0.f; c2[i] = 0.f; }

#define PBAR() asm volatile("bar.sync %0, 64;" :: "r"(barid) : "memory")

    for (int t = 0; t < TSEQ; t++) {
        const int tc = t & (CHUNK - 1);
        if (tc == 0) {
            PBAR();
            if (t) {
                const int t0 = t - CHUNK;
                for (int idx = ptid; idx < 256; idx += 64) {
                    int rl = idx >> 4, c = idx & 15, row = mt * 16 + rl;
                    out[(rb + row) * TSEQ + t0 + c] = lds32(s0 + OFF_YS + (row * XSTR + c) * 4);
                }
            }
            for (int idx = ptid; idx < 256; idx += 64) {
                int rl = idx >> 4, c = idx & 15, row = mt * 16 + rl;
                sts32(s0 + OFF_XS + (row * XSTR + c) * 4, x[(rb + row) * TSEQ + t + c]);
            }
            PBAR();
        }
        if (ptid < 16) {
            int row = mt * 16 + ptid;
            sts16h(s0 + OFF_A1 + (row * ST1 + 52) * 2,
                   lds32(s0 + OFF_XS + (row * XSTR + tc) * 4));
        }
        PBAR();

        uint32_t af[KC2][4];
        float d[13][4];
#pragma unroll
        for (int kc = 0; kc < KC1; kc++) {
            uint32_t base = a1p + kc * 32;
            af[kc][0] = lds32u(base);
            af[kc][1] = lds32u(base + 8 * ST1 * 2);
            af[kc][2] = lds32u(base + 16);
            af[kc][3] = lds32u(base + 8 * ST1 * 2 + 16);
        }
#pragma unroll
        for (int j = 0; j < 13; j++) {
            d[j][0] = d[j][1] = d[j][2] = d[j][3] = 0.f;
#pragma unroll
            for (int kc = 0; kc < KC1; kc++) {
                uint32_t b0, b1;
                lds64u(b0, b1, b1p + (j * KC1 + kc) * 256);
                hmma(d[j], af[kc], b0, b1);
            }
        }
#pragma unroll
        for (int j = 0; j < 13; j++) {
            float t0s = odd ? d[j][0] : d[j][2];
            float t1s = odd ? d[j][1] : d[j][3];
            float rx0 = __shfl_xor_sync(0xffffffffu, t0s, 1);
            float rx1 = __shfl_xor_sync(0xffffffffu, t1s, 1);
            float gi = odd ? rx0 : d[j][0];
            float gf = odd ? rx1 : d[j][1];
            float gg = odd ? d[j][2] : rx0;
            float go = odd ? d[j][3] : rx1;
            float c = fmaf(fsig(gf), c1[j], fsig(gi) * ftanh_(gg));
            c1[j] = c;
            float h = fsig(go) * ftanh_(c);
            sts16h(hw1 + 4 * j, h);
            sts16h(hw2 + 4 * j, h);
        }
        PBAR();

#pragma unroll
        for (int kc = 0; kc < KC2; kc++) {
            uint32_t base = a2p + kc * 32;
            af[kc][0] = lds32u(base);
            af[kc][1] = lds32u(base + 8 * ST2 * 2);
            af[kc][2] = lds32u(base + 16);
            af[kc][3] = lds32u(base + 8 * ST2 * 2 + 16);
        }
#pragma unroll
        for (int j = 0; j < 13; j++) {
            d[j][0] = d[j][1] = d[j][2] = d[j][3] = 0.f;
#pragma unroll
            for (int kc = 0; kc < KC2; kc++) {
                uint32_t b0, b1;
                lds64u(b0, b1, b2p + (j * KC2 + kc) * 256);
                hmma(d[j], af[kc], b0, b1);
            }
        }
        float yp = 0.f;
#pragma unroll
        for (int j = 0; j < 13; j++) {
            float t0s = odd ? d[j][0] : d[j][2];
            float t1s = odd ? d[j][1] : d[j][3];
            float rx0 = __shfl_xor_sync(0xffffffffu, t0s, 1);
            float rx1 = __shfl_xor_sync(0xffffffffu, t1s, 1);
            float gi = odd ? rx0 : d[j][0];
            float gf = odd ? rx1 : d[j][1];
            float gg = odd ? d[j][2] : rx0;
            float go = odd ? d[j][3] : rx1;
            float c = fmaf(fsig(gf), c2[j], fsig(gi) * ftanh_(gg));
            c2[j] = c;
            float h = fsig(go) * ftanh_(c);
            sts16h(hw2 + 104 + 4 * j, h);     // A2 col 52 + ubase + 2j
            yp = fmaf(h, wl[j], yp);
        }
        sts32(s0 + OFF_YP + (rowE * 4 + nh * 2 + ((lane >> 1) & 1)) * 4, yp);
        PBAR();
        if (ptid < 16) {
            int row = mt * 16 + ptid;
            uint32_t ypb = s0 + OFF_YP + row * 16;
            float y = lds32(ypb) + lds32(ypb + 4) + lds32(ypb + 8) + lds32(ypb + 12) + bl;
            sts32(s0 + OFF_YS + (row * XSTR + tc) * 4, y);
        }
    }

    PBAR();
    for (int idx = ptid; idx < 256; idx += 64) {
        int rl = idx >> 4, c = idx & 15, row = mt * 16 + rl;
        out[(rb + row) * TSEQ + (TSEQ - CHUNK) + c] = lds32(s0 + OFF_YS + (row * XSTR + c) * 4);
    }
#undef PBAR
}

extern "C" void kernel_launch(void* const* d_in, const int* in_sizes, int n_in,
                              void* d_out, int out_size) {
    const float* x    = (const float*)d_in[0];
    const float* Wih1 = (const float*)d_in[1];
    const float* Whh1 = (const float*)d_in[2];
    const float* bih1 = (const float*)d_in[3];
    const float* bhh1 = (const float*)d_in[4];
    const float* Wih2 = (const float*)d_in[5];
    const float* Whh2 = (const float*)d_in[6];
    const float* bih2 = (const float*)d_in[7];
    const float* bhh2 = (const float*)d_in[8];
    const float* Wlin = (const float*)d_in[9];
    const float* blin = (const float*)d_in[10];

    cudaFuncSetAttribute(lstm2_hmma_kernel,
                         cudaFuncAttributeMaxDynamicSharedMemorySize, SMEM_BYTES);
    lstm2_hmma_kernel<<<NCTA, NTH, SMEM_BYTES>>>(
        x, Wih1, Whh1, bih1, bhh1, Wih2, Whh2, bih2, bhh2, Wlin, blin,
        (float*)d_out);
}

// round 6
// speedup vs baseline: 7.1819x; 1.2336x over previous
#include <cuda_runtime.h>
#include <cuda_fp16.h>
#include <cstdint>

#define NS    51
#define ROWS  64
#define TSEQ  2048
#define BATCH 8192
#define NCTA  (BATCH / ROWS)
#define NTH   256
#define NTILE 26
#define KC1   4
#define KC2   7
#define ST1   72
#define ST2   120
#define CHUNK 16
#define XSTR  17

#define OFF_A1   0
#define OFF_A2   9216
#define OFF_B1F  24576
#define OFF_B2F  51200
#define OFF_XS   97792
#define OFF_YS   102144
#define OFF_YP   106496
#define OFF_WL   107520
#define SMEM_BYTES 107904

__device__ __forceinline__ uint32_t smem_u32(const void* p) {
    uint32_t a;
    asm("{ .reg .u64 t; cvta.to.shared.u64 t, %1; cvt.u32.u64 %0, t; }" : "=r"(a) : "l"(p));
    return a;
}
__device__ __forceinline__ void sts16h(uint32_t a, float v) {
    unsigned short h = __half_as_ushort(__float2half_rn(v));
    asm volatile("st.shared.b16 [%0], %1;" :: "r"(a), "h"(h) : "memory");
}
__device__ __forceinline__ void sts32(uint32_t a, float v) {
    asm volatile("st.shared.b32 [%0], %1;" :: "r"(a), "f"(v) : "memory");
}
__device__ __forceinline__ void sts32u(uint32_t a, uint32_t v) {
    asm volatile("st.shared.b32 [%0], %1;" :: "r"(a), "r"(v) : "memory");
}
__device__ __forceinline__ float lds32(uint32_t a) {
    float v;
    asm volatile("ld.shared.b32 %0, [%1];" : "=f"(v) : "r"(a));
    return v;
}
__device__ __forceinline__ void lds64u(uint32_t& v0, uint32_t& v1, uint32_t a) {
    asm volatile("ld.shared.v2.b32 {%0,%1}, [%2];" : "=r"(v0), "=r"(v1) : "r"(a));
}
__device__ __forceinline__ void ldsm4(uint32_t* r, uint32_t a) {
    asm volatile("ldmatrix.sync.aligned.m8n8.x4.shared.b16 {%0,%1,%2,%3}, [%4];"
                 : "=r"(r[0]), "=r"(r[1]), "=r"(r[2]), "=r"(r[3]) : "r"(a));
}
__device__ __forceinline__ void hmma(float* d, const uint32_t* a, uint32_t b0, uint32_t b1) {
    asm volatile(
        "mma.sync.aligned.m16n8k16.row.col.f32.f16.f16.f32 "
        "{%0,%1,%2,%3}, {%4,%5,%6,%7}, {%8,%9}, {%0,%1,%2,%3};"
        : "+f"(d[0]), "+f"(d[1]), "+f"(d[2]), "+f"(d[3])
        : "r"(a[0]), "r"(a[1]), "r"(a[2]), "r"(a[3]), "r"(b0), "r"(b1));
}
__device__ __forceinline__ float ex2_(float x) {
    float r;
    asm("ex2.approx.ftz.f32 %0, %1;" : "=f"(r) : "f"(x));
    return r;
}
__device__ __forceinline__ float rcp_(float x) {
    float r;
    asm("rcp.approx.ftz.f32 %0, %1;" : "=f"(r) : "f"(x));
    return r;
}
// Merged LSTM cell update: 5 ex2 + 2 rcp (vs 10 MUFU ops in split form).
// c' = [c(1+a)(1+b) + (1-b)(1+u)] / [(1+a)(1+b)(1+u)],  a=e^-i, b=e^-2g, u=e^-f
// h  = (1-d2) / [(1+o)(1+d2)],  o=e^-go, d2=e^-2c'
__device__ __forceinline__ float cell(float gi, float gf, float gg, float go, float& c) {
    const float L2E = 1.4426950408889634f;
    float a = ex2_(-L2E * gi);
    float b = ex2_(-2.f * L2E * gg);
    float u = ex2_(-L2E * gf);
    float pa = 1.f + a, pb = 1.f + b, pu = 1.f + u;
    float papb = pa * pb;
    float num = fmaf(1.f - b, pu, c * papb);
    c = num * rcp_(papb * pu);
    float o = ex2_(-L2E * go);
    float d2 = ex2_(-2.f * L2E * c);
    return (1.f - d2) * rcp_((1.f + o) * (1.f + d2));
}

__device__ float w1val(int n, int k, const float* Whh1, const float* Wih1,
                       const float* bih1, const float* bhh1) {
    int u = n >> 2, g = n & 3;
    if (u >= NS) return 0.f;
    int gu = g * NS + u;
    if (k < NS) return Whh1[gu * NS + k];
    if (k == 52) return Wih1[gu];
    if (k == 53) return bih1[gu] + bhh1[gu];
    return 0.f;
}
__device__ float w2val(int n, int k, const float* Wih2, const float* Whh2,
                       const float* bih2, const float* bhh2) {
    int u = n >> 2, g = n & 3;
    if (u >= NS) return 0.f;
    int gu = g * NS + u;
    if (k < NS) return Wih2[gu * NS + k];
    if (k >= 52 && k - 52 < NS) return Whh2[gu * NS + (k - 52)];
    if (k == 104) return bih2[gu] + bhh2[gu];
    return 0.f;
}

extern __shared__ char smraw[];

__global__ __launch_bounds__(NTH, 1)
void lstm2_hmma_kernel(const float* __restrict__ x,
                       const float* __restrict__ Wih1, const float* __restrict__ Whh1,
                       const float* __restrict__ bih1, const float* __restrict__ bhh1,
                       const float* __restrict__ Wih2, const float* __restrict__ Whh2,
                       const float* __restrict__ bih2, const float* __restrict__ bhh2,
                       const float* __restrict__ Wlin, const float* __restrict__ blin,
                       float* __restrict__ out) {
    const uint32_t s0 = smem_u32(smraw);
    const int tid = threadIdx.x;
    const int wid = tid >> 5;
    const int lane = tid & 31;

    // ---- one-time pack ----
    for (int i = tid; i < OFF_B1F / 4; i += NTH) sts32(s0 + i * 4, 0.f);
    for (int idx = tid; idx < NTILE * KC1 * 64; idx += NTH) {
        int w = idx & 1, ln = (idx >> 1) & 31, kc = (idx >> 6) & 3, nt = idx >> 8;
        int n = nt * 8 + (ln >> 2);
        int k = kc * 16 + (ln & 3) * 2 + w * 8;
        __half2 hv = __floats2half2_rn(w1val(n, k, Whh1, Wih1, bih1, bhh1),
                                       w1val(n, k + 1, Whh1, Wih1, bih1, bhh1));
        sts32u(s0 + OFF_B1F + idx * 4, *reinterpret_cast<uint32_t*>(&hv));
    }
    for (int idx = tid; idx < NTILE * KC2 * 64; idx += NTH) {
        int w = idx & 1, ln = (idx >> 1) & 31;
        int r = idx >> 6;
        int kc = r % KC2, nt = r / KC2;
        int n = nt * 8 + (ln >> 2);
        int k = kc * 16 + (ln & 3) * 2 + w * 8;
        __half2 hv = __floats2half2_rn(w2val(n, k, Wih2, Whh2, bih2, bhh2),
                                       w2val(n, k + 1, Wih2, Whh2, bih2, bhh2));
        sts32u(s0 + OFF_B2F + ((nt * KC2 + kc) * 64 + ln * 2 + w) * 4,
               *reinterpret_cast<uint32_t*>(&hv));
    }
    if (tid < ROWS) {
        sts16h(s0 + OFF_A1 + (tid * ST1 + 53) * 2, 1.f);
        sts16h(s0 + OFF_A2 + (tid * ST2 + 104) * 2, 1.f);
    }
    for (int u = tid; u < 52; u += NTH)
        sts32(s0 + OFF_WL + u * 4, (u < NS) ? Wlin[u] : 0.f);
    __syncthreads();

    // ---- mapping ----
    const int mt = wid & 3;
    const int nh = wid >> 2;
    const int ptid = nh * 32 + lane;
    const int barid = mt + 1;
    const bool odd = lane & 1;
    const int rowE = mt * 16 + (lane >> 2) + (odd ? 8 : 0);
    const int ubase = 26 * nh + ((lane >> 1) & 1);
    const long long rb = (long long)blockIdx.x * ROWS;
    const float bl = blin[0];

    // ldmatrix lane addresses (lane&15 -> row, lane>>4 -> k-half)
    const int lrow = mt * 16 + (lane & 15);
    const uint32_t khalf = ((lane >> 4) & 1) * 16;
    const uint32_t a1m = s0 + OFF_A1 + lrow * ST1 * 2 + khalf;
    const uint32_t a2m = s0 + OFF_A2 + lrow * ST2 * 2 + khalf;
    const uint32_t b1p = s0 + OFF_B1F + (nh * 13 * KC1 * 64 + lane * 2) * 4;
    const uint32_t b2p = s0 + OFF_B2F + (nh * 13 * KC2 * 64 + lane * 2) * 4;
    const uint32_t hwA1 = s0 + OFF_A1 + rowE * ST1 * 2 + ubase * 2;       // h1 -> A1
    const uint32_t hwA2 = s0 + OFF_A2 + rowE * ST2 * 2 + ubase * 2;       // h1 -> A2
    const uint32_t hwA2b = hwA2 + 104;                                     // h2 -> A2 (col 52+)

    float wl[13];
#pragma unroll
    for (int j = 0; j < 13; j++) wl[j] = lds32(s0 + OFF_WL + (ubase + 2 * j) * 4);

    float c1[13], c2[13], h1v[13], h2v[13];
#pragma unroll
    for (int i = 0; i < 13; i++) { c1[i] = 0.f; c2[i] = 0.f; h1v[i] = 0.f; h2v[i] = 0.f; }

#define PBAR() asm volatile("bar.sync %0, 64;" :: "r"(barid) : "memory")

    for (int t = 0; t < TSEQ; t++) {
        const int tc = t & (CHUNK - 1);

        if (t) {
            // h2(t-1) -> A2 (readers sync at BAR_mid below)
#pragma unroll
            for (int j = 0; j < 13; j++) sts16h(hwA2b + 4 * j, h2v[j]);
            // y(t-1) reduce (YP stable since BAR_end(t-1))
            if (ptid < 16) {
                int row = mt * 16 + ptid;
                uint32_t ypb = s0 + OFF_YP + row * 16;
                float y = lds32(ypb) + lds32(ypb + 4) + lds32(ypb + 8) + lds32(ypb + 12) + bl;
                sts32(s0 + OFF_YS + (row * XSTR + ((t - 1) & (CHUNK - 1))) * 4, y);
            }
        }
        if (tc == 0) {
            PBAR();
            if (t) {
                const int t0 = t - CHUNK;
                for (int idx = ptid; idx < 256; idx += 64) {
                    int rl = idx >> 4, cc = idx & 15, row = mt * 16 + rl;
                    out[(rb + row) * TSEQ + t0 + cc] = lds32(s0 + OFF_YS + (row * XSTR + cc) * 4);
                }
            }
            for (int idx = ptid; idx < 256; idx += 64) {
                int rl = idx >> 4, cc = idx & 15, row = mt * 16 + rl;
                float xv = x[(rb + row) * TSEQ + t + cc];
                sts32(s0 + OFF_XS + (row * XSTR + cc) * 4, xv);
                if (cc == 0) sts16h(s0 + OFF_A1 + (row * ST1 + 52) * 2, xv);
            }
            PBAR();
        }

        // ---- gemm1: A1[64x64] * B1 -> 208 gate cols ----
        uint32_t af[KC2][4];
        float d[13][4];
#pragma unroll
        for (int kc = 0; kc < KC1; kc++) ldsm4(af[kc], a1m + kc * 32);
#pragma unroll
        for (int j = 0; j < 13; j++) {
            d[j][0] = d[j][1] = d[j][2] = d[j][3] = 0.f;
#pragma unroll
            for (int kc = 0; kc < KC1; kc++) {
                uint32_t b0, b1;
                lds64u(b0, b1, b1p + (j * KC1 + kc) * 256);
                hmma(d[j], af[kc], b0, b1);
            }
        }
        // ---- epilogue 1: h1 -> A2 now (gemm2 needs it); A1 store deferred past BAR_mid
#pragma unroll
        for (int j = 0; j < 13; j++) {
            float t0s = odd ? d[j][0] : d[j][2];
            float t1s = odd ? d[j][1] : d[j][3];
            float rx0 = __shfl_xor_sync(0xffffffffu, t0s, 1);
            float rx1 = __shfl_xor_sync(0xffffffffu, t1s, 1);
            float gi = odd ? rx0 : d[j][0];
            float gf = odd ? rx1 : d[j][1];
            float gg = odd ? d[j][2] : rx0;
            float go = odd ? d[j][3] : rx1;
            float h = cell(gi, gf, gg, go, c1[j]);
            h1v[j] = h;
            sts16h(hwA2 + 4 * j, h);
        }
        PBAR();   // BAR_mid: h1/A2 + h2/A2 visible; all gemm1 A-reads complete

        // h1 -> A1 for gemm1(t+1) (no A1 readers until BAR_end)
#pragma unroll
        for (int j = 0; j < 13; j++) sts16h(hwA1 + 4 * j, h1v[j]);

        // ---- gemm2: A2[64x112] * B2 ----
#pragma unroll
        for (int kc = 0; kc < KC2; kc++) ldsm4(af[kc], a2m + kc * 32);
#pragma unroll
        for (int j = 0; j < 13; j++) {
            d[j][0] = d[j][1] = d[j][2] = d[j][3] = 0.f;
#pragma unroll
            for (int kc = 0; kc < KC2; kc++) {
                uint32_t b0, b1;
                lds64u(b0, b1, b2p + (j * KC2 + kc) * 256);
                hmma(d[j], af[kc], b0, b1);
            }
        }
        // ---- epilogue 2: h2 in regs (stored next step); yp; x(t+1) ----
        float yp = 0.f;
#pragma unroll
        for (int j = 0; j < 13; j++) {
            float t0s = odd ? d[j][0] : d[j][2];
            float t1s = odd ? d[j][1] : d[j][3];
            float rx0 = __shfl_xor_sync(0xffffffffu, t0s, 1);
            float rx1 = __shfl_xor_sync(0xffffffffu, t1s, 1);
            float gi = odd ? rx0 : d[j][0];
            float gf = odd ? rx1 : d[j][1];
            float gg = odd ? d[j][2] : rx0;
            float go = odd ? d[j][3] : rx1;
            float h = cell(gi, gf, gg, go, c2[j]);
            h2v[j] = h;
            yp = fmaf(h, wl[j], yp);
        }
        sts32(s0 + OFF_YP + (rowE * 4 + nh * 2 + ((lane >> 1) & 1)) * 4, yp);
        if (tc < CHUNK - 1 && ptid < 16) {
            int row = mt * 16 + ptid;
            sts16h(s0 + OFF_A1 + (row * ST1 + 52) * 2,
                   lds32(s0 + OFF_XS + (row * XSTR + tc + 1) * 4));
        }
        PBAR();   // BAR_end
    }

    // final y(T-1) + last chunk flush
    if (ptid < 16) {
        int row = mt * 16 + ptid;
        uint32_t ypb = s0 + OFF_YP + row * 16;
        float y = lds32(ypb) + lds32(ypb + 4) + lds32(ypb + 8) + lds32(ypb + 12) + bl;
        sts32(s0 + OFF_YS + (row * XSTR + (CHUNK - 1)) * 4, y);
    }
    PBAR();
    for (int idx = ptid; idx < 256; idx += 64) {
        int rl = idx >> 4, cc = idx & 15, row = mt * 16 + rl;
        out[(rb + row) * TSEQ + (TSEQ - CHUNK) + cc] = lds32(s0 + OFF_YS + (row * XSTR + cc) * 4);
    }
#undef PBAR
}

extern "C" void kernel_launch(void* const* d_in, const int* in_sizes, int n_in,
                              void* d_out, int out_size) {
    const float* x    = (const float*)d_in[0];
    const float* Wih1 = (const float*)d_in[1];
    const float* Whh1 = (const float*)d_in[2];
    const float* bih1 = (const float*)d_in[3];
    const float* bhh1 = (const float*)d_in[4];
    const float* Wih2 = (const float*)d_in[5];
    const float* Whh2 = (const float*)d_in[6];
    const float* bih2 = (const float*)d_in[7];
    const float* bhh2 = (const float*)d_in[8];
    const float* Wlin = (const float*)d_in[9];
    const float* blin = (const float*)d_in[10];

    cudaFuncSetAttribute(lstm2_hmma_kernel,
                         cudaFuncAttributeMaxDynamicSharedMemorySize, SMEM_BYTES);
    lstm2_hmma_kernel<<<NCTA, NTH, SMEM_BYTES>>>(
        x, Wih1, Whh1, bih1, bhh1, Wih2, Whh2, bih2, bhh2, Wlin, blin,
        (float*)d_out);
}